// round 6
// baseline (speedup 1.0000x reference)
#include <cuda_runtime.h>

// Problem constants (fixed per metadata)
#define EMAX 160000
#define NMAX 10000

// Scratch (device globals — allocation-free)
__device__ float g_ex[EMAX * 4];      // exp(score) per edge/head
__device__ float g_v[EMAX * 24];      // v per edge (m2*d2 = 24)
__device__ float g_denom[NMAX * 4];   // softmax denominator per node/head

// Packed fp32x2 FMA (Blackwell): d.lo += a.lo*b.lo ; d.hi += a.hi*b.hi
#define FMA_F32X2(d, a, b) \
    asm("fma.rn.f32x2 %0, %1, %2, %0;" : "+l"(d) : "l"(a), "l"(b))

// Shared memory layout (in floats)
#define OFF_W2S 0        // [768][64]  W2 original layout, quad-XOR swizzled rows
#define OFF_W1S 49152    // [64][32]   W1 original layout (k contiguous)
#define OFF_H   51200    // [32][64]   H e-major, quad-XOR swizzled rows
#define OFF_BAS 53248    // [32][18]   basis per edge
#define OFF_FG  53824    // [32][48]   gathered f[src]
#define OFF_UNI 55360    // union: EF [32][34] (1088) / conv [32][72] (2304)
#define OFF_SRC 57664    // [32] int
#define OFF_DST 57696    // [32] int
#define SMEM_FLOATS 57728
#define SMEM_BYTES (SMEM_FLOATS * 4)   // 230912 B

#define NTHR 512

__global__ __launch_bounds__(NTHR, 1)
void passA(const int* __restrict__ src, const int* __restrict__ dst,
           const float* __restrict__ basis, const float* __restrict__ efeat,
           const float* __restrict__ f, const float* __restrict__ W1,
           const float* __restrict__ b1, const float* __restrict__ W2,
           const float* __restrict__ b2, int E)
{
    extern __shared__ float sm[];
    float* W2s = sm + OFF_W2S;
    float* W1s = sm + OFF_W1S;
    float* Hs  = sm + OFF_H;
    float* bas = sm + OFF_BAS;
    float* fg  = sm + OFF_FG;
    float* uni = sm + OFF_UNI;
    int* srcs  = (int*)(sm + OFF_SRC);
    int* dsts  = (int*)(sm + OFF_DST);

    const int t = threadIdx.x;

    // ---- one-time per block: stage W2 (quad-swizzled, k-contiguous) and W1 ----
    for (int idx = t; idx < 768 * 64; idx += NTHR) {
        int o = idx >> 6, k = idx & 63;
        int q = k >> 2, key = (o >> 2) & 7;
        W2s[(o << 6) | ((q ^ key) << 2) | (k & 3)] = W2[idx];
    }
    for (int idx = t; idx < 64 * 32; idx += NTHR)
        W1s[idx] = W1[idx];
    __syncthreads();

    // GEMM thread mapping: 4 c-quadrants x (16 e-groups x 8 m-groups)
    const int cq = t >> 7;          // 0..3
    const int ty = (t >> 3) & 15;   // 0..15
    const int tx = t & 7;           // 0..7
    const int e0 = ty * 2;          // 2 edges per thread
    const int m0 = tx * 4;          // 4 m per thread
    const int keyA = (e0 >> 2) & 7; // both edges in same quad (e0 even)
    const int keyB = tx & 7;        // (m0>>2)&7 = tx

    const int ntiles = (E + 31) >> 5;
    for (int tile = blockIdx.x; tile < ntiles; tile += gridDim.x) {
        const int eg0 = tile << 5;

        // ---- stage 1: edge indices ----
        if (t < 32) {
            int ee = min(eg0 + t, E - 1);
            srcs[t] = src[ee];
            dsts[t] = dst[ee];
        }
        __syncthreads();

        // ---- stage 2: edge feats (union region, [32][34] pad), basis, gathered f ----
        for (int idx = t; idx < 1024; idx += NTHR) {
            int e = idx >> 5, i = idx & 31;
            int ee = min(eg0 + e, E - 1);
            uni[e * 34 + i] = efeat[ee * 32 + i];
        }
        for (int idx = t; idx < 576; idx += NTHR) {      // basis [32][18]
            int e = idx / 18, k = idx - e * 18;
            int ee = min(eg0 + e, E - 1);
            bas[e * 18 + k] = basis[ee * 18 + k];
        }
        for (int idx = t; idx < 1536; idx += NTHR) {     // f gather [32][48]
            int e = idx / 48, r = idx - e * 48;
            fg[idx] = f[srcs[e] * 48 + r];
        }
        __syncthreads();

        // ---- stage 3a: tmp[e][m][d] into registers (24/thread) ----
        float tmpreg[2][4][3];
        #pragma unroll
        for (int ie = 0; ie < 2; ie++) {
            int e = e0 + ie;
            #pragma unroll
            for (int im = 0; im < 4; im++) {
                int m = m0 + im;
                int m1 = m >> 1, rep = m & 1;
                #pragma unroll
                for (int d = 0; d < 3; d++) {
                    float s = 0.f;
                    #pragma unroll
                    for (int d1 = 0; d1 < 3; d1++)
                        s += fg[e * 48 + m1 * 3 + d1] * bas[e * 18 + d1 * 6 + rep * 3 + d];
                    tmpreg[ie][im][d] = s;
                }
            }
        }

        // ---- stage 3b: H = relu(EF @ W1^T + b1), packed f32x2 over k-pairs ----
        {
            int e = t & 31;
            int jg = t >> 5;          // 0..15, 4 j's each
            unsigned long long ef[16];
            #pragma unroll
            for (int p = 0; p < 16; p++)
                ef[p] = *reinterpret_cast<const unsigned long long*>(uni + e * 34 + p * 2);
            int ekey = (e >> 2) & 7;
            #pragma unroll
            for (int jj = 0; jj < 4; jj++) {
                int j = jg * 4 + jj;
                const float* wrow = W1s + j * 32;
                unsigned long long acc = 0ull;
                #pragma unroll
                for (int p = 0; p < 16; p++) {
                    unsigned long long w =
                        *reinterpret_cast<const unsigned long long*>(wrow + p * 2);
                    FMA_F32X2(acc, ef[p], w);
                }
                float lo = __uint_as_float((unsigned)acc);
                float hi = __uint_as_float((unsigned)(acc >> 32));
                float a = lo + hi + __ldg(&b1[j]);
                Hs[(e << 6) | ((((j >> 2) ^ ekey) << 2) | (j & 3))] = fmaxf(a, 0.f);
            }
        }
        __syncthreads();   // Hs ready; EF (union) now dead -> conv may overwrite

        // ---- stage 4: RW GEMM (f32x2 packed, k-pair accumulators) + conv fuse ----
        float* conv = uni;   // [32][72]
        #pragma unroll 1
        for (int cg = 0; cg < 6; cg++) {
            const int c = cg * 4 + cq;
            unsigned long long acc2[2][4];
            #pragma unroll
            for (int ie = 0; ie < 2; ie++)
                #pragma unroll
                for (int im = 0; im < 4; im++)
                    acc2[ie][im] = 0ull;

            const float* Wb = W2s + (c * 32 + m0) * 64;
            #pragma unroll
            for (int q = 0; q < 16; q++) {
                const int qa = (q ^ keyA) << 2;
                const int qb = (q ^ keyB) << 2;
                ulonglong2 a[2], b[4];
                #pragma unroll
                for (int ie = 0; ie < 2; ie++)
                    a[ie] = *reinterpret_cast<const ulonglong2*>(Hs + ((e0 + ie) << 6) + qa);
                #pragma unroll
                for (int im = 0; im < 4; im++)
                    b[im] = *reinterpret_cast<const ulonglong2*>(Wb + (im << 6) + qb);
                #pragma unroll
                for (int ie = 0; ie < 2; ie++)
                    #pragma unroll
                    for (int im = 0; im < 4; im++) {
                        FMA_F32X2(acc2[ie][im], a[ie].x, b[im].x);
                        FMA_F32X2(acc2[ie][im], a[ie].y, b[im].y);
                    }
            }

            // epilogue: rw = lo+hi+bias; fuse conv partial
            float bvals[4];
            #pragma unroll
            for (int im = 0; im < 4; im++)
                bvals[im] = __ldg(&b2[c * 32 + m0 + im]);

            float pc[2][3];
            #pragma unroll
            for (int ie = 0; ie < 2; ie++) { pc[ie][0] = 0.f; pc[ie][1] = 0.f; pc[ie][2] = 0.f; }
            #pragma unroll
            for (int ie = 0; ie < 2; ie++)
                #pragma unroll
                for (int im = 0; im < 4; im++) {
                    unsigned long long v = acc2[ie][im];
                    float r = __uint_as_float((unsigned)v)
                            + __uint_as_float((unsigned)(v >> 32)) + bvals[im];
                    pc[ie][0] += r * tmpreg[ie][im][0];
                    pc[ie][1] += r * tmpreg[ie][im][1];
                    pc[ie][2] += r * tmpreg[ie][im][2];
                }
            // reduce over the 8 m-groups (tx = lane bits 0..2) within one warp
            #pragma unroll
            for (int off = 1; off < 8; off <<= 1)
                #pragma unroll
                for (int ie = 0; ie < 2; ie++)
                    #pragma unroll
                    for (int d = 0; d < 3; d++)
                        pc[ie][d] += __shfl_xor_sync(0xffffffffu, pc[ie][d], off);
            if (tx == 0) {
                #pragma unroll
                for (int ie = 0; ie < 2; ie++)
                    #pragma unroll
                    for (int d = 0; d < 3; d++)
                        conv[(e0 + ie) * 72 + c * 3 + d] = pc[ie][d];
            }
        }
        __syncthreads();

        // ---- stage 5: attention scores, exp, denom atomics, stash v ----
        if (t < 256) {
            int e = t >> 3, s = t & 7;   // 32 edges x 8 threads
            int ge = eg0 + e;
            if (ge < E) {
                if (s < 4) {   // s = head
                    float sc = 0.f;
                    #pragma unroll
                    for (int hd = 0; hd < 6; hd++)
                        sc += conv[e * 72 + s * 6 + hd] * conv[e * 72 + 24 + s * 6 + hd];
                    sc *= 0.20412414523193154f;           // 24^-0.5
                    sc = (sc >= 0.f) ? sc : 0.2f * sc;    // leaky_relu(0.2)
                    float ex = expf(sc);                  // shift-invariant softmax (scores ~O(1))
                    g_ex[ge * 4 + s] = ex;
                    atomicAdd(&g_denom[dsts[e] * 4 + s], ex);
                }
                #pragma unroll
                for (int jj = 0; jj < 3; jj++)
                    g_v[ge * 24 + s * 3 + jj] = conv[e * 72 + 48 + s * 3 + jj];
            }
        }
        __syncthreads();
    }
}

__global__ void initK(float* __restrict__ out, int N)
{
    int i = blockIdx.x * blockDim.x + threadIdx.x;
    if (i < N * 24) out[i] = 0.f;
    if (i < N * 4)  g_denom[i] = 0.f;
}

__global__ __launch_bounds__(256)
void passB(const int* __restrict__ dst, float* __restrict__ out, int E)
{
    int idx = blockIdx.x * blockDim.x + threadIdx.x;
    int e = idx >> 3, s = idx & 7;      // 8 threads/edge, 3 outputs each
    if (e >= E) return;
    int d = dst[e];
    int head = s >> 1;                   // 6 floats/head, 3 per thread
    float w = g_ex[e * 4 + head] / g_denom[d * 4 + head];
    #pragma unroll
    for (int jj = 0; jj < 3; jj++) {
        int j = s * 3 + jj;
        atomicAdd(&out[d * 24 + j], w * g_v[e * 24 + j]);
    }
}

extern "C" void kernel_launch(void* const* d_in, const int* in_sizes, int n_in,
                              void* d_out, int out_size)
{
    const int*   src   = (const int*)d_in[0];
    const int*   dst   = (const int*)d_in[1];
    const float* basis = (const float*)d_in[2];
    const float* efeat = (const float*)d_in[3];
    const float* f     = (const float*)d_in[4];
    const float* W1    = (const float*)d_in[5];
    const float* b1    = (const float*)d_in[6];
    const float* W2    = (const float*)d_in[7];
    const float* b2    = (const float*)d_in[8];
    float* out = (float*)d_out;

    int E = in_sizes[0];          // 160000
    int N = in_sizes[4] / 48;     // f is (N,16,3) -> 10000

    cudaFuncSetAttribute(passA, cudaFuncAttributeMaxDynamicSharedMemorySize, SMEM_BYTES);

    initK<<<(N * 24 + 255) / 256, 256>>>(out, N);

    int ntiles = (E + 31) / 32;
    int grid = ntiles < 148 ? ntiles : 148;
    passA<<<grid, NTHR, SMEM_BYTES>>>(src, dst, basis, efeat, f, W1, b1, W2, b2, E);

    passB<<<(E * 8 + 255) / 256, 256>>>(dst, out, E);
}

// round 7
// speedup vs baseline: 1.5235x; 1.5235x over previous
#include <cuda_runtime.h>

// Problem constants (fixed per metadata)
#define EMAX 160000
#define NMAX 10000

// Scratch (device globals — allocation-free)
__device__ float g_ex[EMAX * 4];      // exp(score) per edge/head
__device__ float g_v[EMAX * 24];      // v per edge (m2*d2 = 24)
__device__ float g_denom[NMAX * 4];   // softmax denominator per node/head

// Packed fp32x2 FMA (Blackwell): d.lo += a.lo*b.lo ; d.hi += a.hi*b.hi
#define FMA_F32X2(d, a, b) \
    asm("fma.rn.f32x2 %0, %1, %2, %0;" : "+l"(d) : "l"(a), "l"(b))

// Shared memory layout (in floats)
#define OFF_W2S 0        // [768][64]  W2 original layout, quad-XOR swizzled rows
#define OFF_W1S 49152    // [64][32]   W1 original layout (k contiguous)
#define OFF_H   51200    // [32][64]   H e-major, quad-XOR swizzled rows
#define OFF_BAS 53248    // [32][18]   basis per edge
#define OFF_FG  53824    // [32][48]   gathered f[src]
#define OFF_UNI 55360    // union: EF [32][34] (1088) / conv [32][72] (2304)
#define OFF_SRC 57664    // [32] int
#define OFF_DST 57696    // [32] int
#define SMEM_FLOATS 57728
#define SMEM_BYTES (SMEM_FLOATS * 4)   // 230912 B

#define NTHR 256

__global__ __launch_bounds__(NTHR, 1)
void passA(const int* __restrict__ src, const int* __restrict__ dst,
           const float* __restrict__ basis, const float* __restrict__ efeat,
           const float* __restrict__ f, const float* __restrict__ W1,
           const float* __restrict__ b1, const float* __restrict__ W2,
           const float* __restrict__ b2, int E)
{
    extern __shared__ float sm[];
    float* W2s = sm + OFF_W2S;
    float* W1s = sm + OFF_W1S;
    float* Hs  = sm + OFF_H;
    float* bas = sm + OFF_BAS;
    float* fg  = sm + OFF_FG;
    float* uni = sm + OFF_UNI;
    int* srcs  = (int*)(sm + OFF_SRC);
    int* dsts  = (int*)(sm + OFF_DST);

    const int t = threadIdx.x;

    // ---- one-time per block: stage W2 (quad-swizzled, k-contiguous) and W1 ----
    for (int idx = t; idx < 768 * 64; idx += NTHR) {
        int o = idx >> 6, k = idx & 63;
        int q = k >> 2, key = (o >> 2) & 7;
        W2s[(o << 6) | ((q ^ key) << 2) | (k & 3)] = W2[idx];
    }
    for (int idx = t; idx < 64 * 32; idx += NTHR)
        W1s[idx] = W1[idx];
    __syncthreads();

    // GEMM thread mapping: 4 c-pair groups x (8 e-groups x 8 m-groups)
    const int cq = t >> 6;          // 0..3 (c-pair group)
    const int ty = (t >> 3) & 7;    // 0..7
    const int tx = t & 7;           // 0..7
    const int e0 = ty * 4;
    const int m0 = tx * 4;
    const int keyA = ty;            // (e0>>2)&7
    const int keyB = tx;            // (m0>>2)&7

    const int ntiles = (E + 31) >> 5;
    for (int tile = blockIdx.x; tile < ntiles; tile += gridDim.x) {
        const int eg0 = tile << 5;

        // ---- stage 1: edge indices ----
        if (t < 32) {
            int ee = min(eg0 + t, E - 1);
            srcs[t] = src[ee];
            dsts[t] = dst[ee];
        }
        __syncthreads();

        // ---- stage 2: edge feats (union region, [32][34] pad), basis, gathered f ----
        for (int idx = t; idx < 1024; idx += NTHR) {
            int e = idx >> 5, i = idx & 31;
            int ee = min(eg0 + e, E - 1);
            uni[e * 34 + i] = efeat[ee * 32 + i];
        }
        for (int idx = t; idx < 576; idx += NTHR) {      // basis [32][18]
            int e = idx / 18, k = idx - e * 18;
            int ee = min(eg0 + e, E - 1);
            bas[e * 18 + k] = basis[ee * 18 + k];
        }
        for (int idx = t; idx < 1536; idx += NTHR) {     // f gather [32][48]
            int e = idx / 48, r = idx - e * 48;
            fg[idx] = f[srcs[e] * 48 + r];
        }
        __syncthreads();

        // ---- stage 3a: tmp[e][m][d] into registers (48/thread) ----
        float tmpreg[4][4][3];
        #pragma unroll
        for (int ie = 0; ie < 4; ie++) {
            int e = e0 + ie;
            #pragma unroll
            for (int im = 0; im < 4; im++) {
                int m = m0 + im;
                int m1 = m >> 1, rep = m & 1;
                #pragma unroll
                for (int d = 0; d < 3; d++) {
                    float s = 0.f;
                    #pragma unroll
                    for (int d1 = 0; d1 < 3; d1++)
                        s += fg[e * 48 + m1 * 3 + d1] * bas[e * 18 + d1 * 6 + rep * 3 + d];
                    tmpreg[ie][im][d] = s;
                }
            }
        }

        // ---- stage 3b: H = relu(EF @ W1^T + b1), packed f32x2 over k-pairs ----
        {
            int e = t & 31;
            int jg = t >> 5;          // warp id; W1 rows broadcast within warp
            unsigned long long ef[16];
            #pragma unroll
            for (int p = 0; p < 16; p++)
                ef[p] = *reinterpret_cast<const unsigned long long*>(uni + e * 34 + p * 2);
            int ekey = (e >> 2) & 7;
            #pragma unroll
            for (int jj = 0; jj < 8; jj++) {
                int j = jg * 8 + jj;
                const float* wrow = W1s + j * 32;
                unsigned long long acc = 0ull;
                #pragma unroll
                for (int p = 0; p < 16; p++) {
                    unsigned long long w =
                        *reinterpret_cast<const unsigned long long*>(wrow + p * 2);
                    FMA_F32X2(acc, ef[p], w);
                }
                float lo = __uint_as_float((unsigned)acc);
                float hi = __uint_as_float((unsigned)(acc >> 32));
                float a = lo + hi + __ldg(&b1[j]);
                Hs[(e << 6) | ((((j >> 2) ^ ekey) << 2) | (j & 3))] = fmaxf(a, 0.f);
            }
        }
        __syncthreads();   // Hs ready; EF (union) now dead -> conv may overwrite

        // ---- stage 4: RW GEMM, 2 c-channels per pass (A-frag reuse) + conv fuse ----
        float* conv = uni;   // [32][72]
        #pragma unroll 1
        for (int pass = 0; pass < 3; pass++) {
            const int c0 = pass * 8 + cq * 2;      // this thread's c-pair: c0, c0+1
            unsigned long long acc2[2][4][4];      // [ci][ie][im]
            #pragma unroll
            for (int ci = 0; ci < 2; ci++)
                #pragma unroll
                for (int ie = 0; ie < 4; ie++)
                    #pragma unroll
                    for (int im = 0; im < 4; im++)
                        acc2[ci][ie][im] = 0ull;

            const float* Wb0 = W2s + (c0 * 32 + m0) * 64;
            const float* Wb1 = Wb0 + 32 * 64;
            #pragma unroll
            for (int q = 0; q < 16; q++) {
                const int qa = (q ^ keyA) << 2;
                const int qb = (q ^ keyB) << 2;
                ulonglong2 a[4];
                #pragma unroll
                for (int ie = 0; ie < 4; ie++)
                    a[ie] = *reinterpret_cast<const ulonglong2*>(Hs + ((e0 + ie) << 6) + qa);
                ulonglong2 b0[4], b1r[4];
                #pragma unroll
                for (int im = 0; im < 4; im++) {
                    b0[im]  = *reinterpret_cast<const ulonglong2*>(Wb0 + (im << 6) + qb);
                    b1r[im] = *reinterpret_cast<const ulonglong2*>(Wb1 + (im << 6) + qb);
                }
                #pragma unroll
                for (int ie = 0; ie < 4; ie++)
                    #pragma unroll
                    for (int im = 0; im < 4; im++) {
                        FMA_F32X2(acc2[0][ie][im], a[ie].x, b0[im].x);
                        FMA_F32X2(acc2[0][ie][im], a[ie].y, b0[im].y);
                        FMA_F32X2(acc2[1][ie][im], a[ie].x, b1r[im].x);
                        FMA_F32X2(acc2[1][ie][im], a[ie].y, b1r[im].y);
                    }
            }

            // epilogue per c: rw = lo+hi+bias; fuse conv partial; warp-reduce over m
            #pragma unroll
            for (int ci = 0; ci < 2; ci++) {
                const int c = c0 + ci;
                float bvals[4];
                #pragma unroll
                for (int im = 0; im < 4; im++)
                    bvals[im] = __ldg(&b2[c * 32 + m0 + im]);

                float pc[4][3];
                #pragma unroll
                for (int ie = 0; ie < 4; ie++) { pc[ie][0] = 0.f; pc[ie][1] = 0.f; pc[ie][2] = 0.f; }
                #pragma unroll
                for (int ie = 0; ie < 4; ie++)
                    #pragma unroll
                    for (int im = 0; im < 4; im++) {
                        unsigned long long v = acc2[ci][ie][im];
                        float r = __uint_as_float((unsigned)v)
                                + __uint_as_float((unsigned)(v >> 32)) + bvals[im];
                        pc[ie][0] += r * tmpreg[ie][im][0];
                        pc[ie][1] += r * tmpreg[ie][im][1];
                        pc[ie][2] += r * tmpreg[ie][im][2];
                    }
                // reduce over the 8 m-groups (tx = lane bits 0..2) within one warp
                #pragma unroll
                for (int off = 1; off < 8; off <<= 1)
                    #pragma unroll
                    for (int ie = 0; ie < 4; ie++)
                        #pragma unroll
                        for (int d = 0; d < 3; d++)
                            pc[ie][d] += __shfl_xor_sync(0xffffffffu, pc[ie][d], off);
                if (tx == 0) {
                    #pragma unroll
                    for (int ie = 0; ie < 4; ie++)
                        #pragma unroll
                        for (int d = 0; d < 3; d++)
                            conv[(e0 + ie) * 72 + c * 3 + d] = pc[ie][d];
                }
            }
        }
        __syncthreads();

        // ---- stage 5: attention scores, exp, denom atomics, stash v ----
        {
            int e = t >> 3, s = t & 7;   // 32 edges x 8 threads
            int ge = eg0 + e;
            if (ge < E) {
                if (s < 4) {   // s = head
                    float sc = 0.f;
                    #pragma unroll
                    for (int hd = 0; hd < 6; hd++)
                        sc += conv[e * 72 + s * 6 + hd] * conv[e * 72 + 24 + s * 6 + hd];
                    sc *= 0.20412414523193154f;           // 24^-0.5
                    sc = (sc >= 0.f) ? sc : 0.2f * sc;    // leaky_relu(0.2)
                    float ex = expf(sc);                  // shift-invariant softmax (scores ~O(1))
                    g_ex[ge * 4 + s] = ex;
                    atomicAdd(&g_denom[dsts[e] * 4 + s], ex);
                }
                #pragma unroll
                for (int jj = 0; jj < 3; jj++)
                    g_v[ge * 24 + s * 3 + jj] = conv[e * 72 + 48 + s * 3 + jj];
            }
        }
        __syncthreads();
    }
}

__global__ void initK(float* __restrict__ out, int N)
{
    int i = blockIdx.x * blockDim.x + threadIdx.x;
    if (i < N * 24) out[i] = 0.f;
    if (i < N * 4)  g_denom[i] = 0.f;
}

__global__ __launch_bounds__(256)
void passB(const int* __restrict__ dst, float* __restrict__ out, int E)
{
    int idx = blockIdx.x * blockDim.x + threadIdx.x;
    int e = idx >> 3, s = idx & 7;      // 8 threads/edge, 3 outputs each
    if (e >= E) return;
    int d = dst[e];
    int head = s >> 1;                   // 6 floats/head, 3 per thread
    float w = g_ex[e * 4 + head] / g_denom[d * 4 + head];
    #pragma unroll
    for (int jj = 0; jj < 3; jj++) {
        int j = s * 3 + jj;
        atomicAdd(&out[d * 24 + j], w * g_v[e * 24 + j]);
    }
}

extern "C" void kernel_launch(void* const* d_in, const int* in_sizes, int n_in,
                              void* d_out, int out_size)
{
    const int*   src   = (const int*)d_in[0];
    const int*   dst   = (const int*)d_in[1];
    const float* basis = (const float*)d_in[2];
    const float* efeat = (const float*)d_in[3];
    const float* f     = (const float*)d_in[4];
    const float* W1    = (const float*)d_in[5];
    const float* b1    = (const float*)d_in[6];
    const float* W2    = (const float*)d_in[7];
    const float* b2    = (const float*)d_in[8];
    float* out = (float*)d_out;

    int E = in_sizes[0];          // 160000
    int N = in_sizes[4] / 48;     // f is (N,16,3) -> 10000

    cudaFuncSetAttribute(passA, cudaFuncAttributeMaxDynamicSharedMemorySize, SMEM_BYTES);

    initK<<<(N * 24 + 255) / 256, 256>>>(out, N);

    int ntiles = (E + 31) / 32;
    int grid = ntiles < 148 ? ntiles : 148;
    passA<<<grid, NTHR, SMEM_BYTES>>>(src, dst, basis, efeat, f, W1, b1, W2, b2, E);

    passB<<<(E * 8 + 255) / 256, 256>>>(dst, out, E);
}